// round 1
// baseline (speedup 1.0000x reference)
#include <cuda_runtime.h>

#define Bsz   128
#define Tt    512
#define INs   27
#define Hh    256
#define G4    1024
#define NB    128
#define OUTs  128

// ---- persistent device scratch (static: no runtime allocation) ----
__device__ float g_G[(size_t)Tt * G4 * Bsz];   // [t][g(1024)][b]  = x @ W_ih_x^T + b_ih + b_hh
__device__ float g_h[2][Hh * Bsz];             // [k][b], double buffered
__device__ float g_c[Hh * Bsz];                // [k][b]
__device__ unsigned long long g_arrive;        // grid barrier (monotonic)
__device__ unsigned long long g_release;

// ---------------- helpers ----------------
__device__ __forceinline__ void fma2(unsigned long long& d, unsigned long long a, unsigned long long b) {
    asm("fma.rn.f32x2 %0, %1, %2, %0;" : "+l"(d) : "l"(a), "l"(b));
}
__device__ __forceinline__ float f2lo(unsigned long long u) { return __uint_as_float((unsigned)u); }
__device__ __forceinline__ float f2hi(unsigned long long u) { return __uint_as_float((unsigned)(u >> 32)); }

__device__ __forceinline__ float sigf(float x) {
    return __fdividef(1.f, 1.f + __expf(-x));
}
__device__ __forceinline__ float tanhf_(float x) {
    float e = __expf(-2.f * fabsf(x));
    float r = __fdividef(1.f - e, 1.f + e);
    return copysignf(r, x);
}

__device__ __forceinline__ void grid_bar() {
    __syncthreads();
    if (threadIdx.x == 0) {
        unsigned long long old, one = 1ULL;
        asm volatile("atom.acq_rel.gpu.add.u64 %0, [%1], %2;"
                     : "=l"(old) : "l"(&g_arrive), "l"(one) : "memory");
        unsigned long long gen = old >> 7;                 // / NB (NB == 128)
        if ((old & (unsigned long long)(NB - 1)) == (unsigned long long)(NB - 1)) {
            asm volatile("red.release.gpu.add.u64 [%0], %1;"
                         :: "l"(&g_release), "l"(one) : "memory");
        } else {
            unsigned long long cur;
            do {
                asm volatile("ld.acquire.gpu.u64 %0, [%1];"
                             : "=l"(cur) : "l"(&g_release) : "memory");
            } while (cur <= gen);
        }
    }
    __syncthreads();
}

// ---------------- kernels ----------------
__global__ void init_kernel() {
    int i = blockIdx.x * blockDim.x + threadIdx.x;
    if (i < Hh * Bsz) {
        g_h[0][i] = 0.f;
        g_c[i]    = 0.f;
    }
}

// G[t][g][b] = b_ih[g] + b_hh[g] + sum_{k<27} x[b][t][k] * W_ih[g][k]
__global__ void pre_kernel(const float* __restrict__ x,
                           const float* __restrict__ W_ih,
                           const float* __restrict__ b_ih,
                           const float* __restrict__ b_hh) {
    __shared__ float xs[Bsz * INs];
    const int t   = blockIdx.x;
    const int gc  = blockIdx.y;       // 0..7, 128 gates each
    const int tid = threadIdx.x;      // = b
    for (int i = tid; i < Bsz * INs; i += 128) {
        int b = i / INs, k = i - b * INs;
        xs[i] = x[((size_t)b * Tt + t) * INs + k];
    }
    __syncthreads();
    float xr[INs];
    #pragma unroll
    for (int k = 0; k < INs; ++k) xr[k] = xs[tid * INs + k];

    for (int g0 = 0; g0 < 128; ++g0) {
        int g = (gc << 7) + g0;
        float acc = b_ih[g] + b_hh[g];
        const float* wr = W_ih + g * 47;   // NN_IN = 47, only first 27 cols used
        #pragma unroll
        for (int k = 0; k < INs; ++k) acc += xr[k] * __ldg(wr + k);
        g_G[((size_t)t * G4 + g) * Bsz + tid] = acc;
    }
}

// Persistent sequential LSTM. grid = 128 blocks = 4 b-tiles(32) x 32 j-tiles(8).
// Shared: sW [256k][64] (W tile, value-duplicated pairs) loaded once,
//         sH [256k][32b] reloaded per step, sR padded reduce buffer.
__global__ void __launch_bounds__(256, 1)
step_kernel(const float* __restrict__ W_hh,
            const float* __restrict__ W_fc,
            const float* __restrict__ b_fc,
            float* __restrict__ out) {
    extern __shared__ float sm[];
    float* sW = sm;                          // 16384 floats
    float* sH = sm + 256 * 64;               //  8192 floats
    float* sR = sm + 256 * 64 + 256 * 32;    //  4608 floats

    const int tid = threadIdx.x;
    const int bt  = blockIdx.x >> 5;         // 0..3
    const int jt  = blockIdx.x & 31;         // 0..31
    const int b0  = bt << 5;
    const int j0  = jt << 3;

    // ---- load W_hh tile once, duplicated into f32x2 pairs ----
    for (int i = tid; i < 256 * 32; i += 256) {
        int k = i >> 5, r = i & 31;          // r = jl*4 + gate
        int jl = r >> 2, g = r & 3;
        float w = W_hh[(((g << 8) + j0 + jl) << 8) + k];
        sW[(k << 6) + (r << 1)]     = w;
        sW[(k << 6) + (r << 1) + 1] = w;
    }

    // compute-role mapping: 4 k-splits x (8 b-quads x 8 j)
    const int ks   = tid >> 6;
    const int pos  = tid & 63;
    const int bq   = pos & 7;
    const int jl   = pos >> 3;
    const int hoff = bq << 2;
    const int woff = jl << 3;
    const int kb   = ks << 6;

    // epilogue-role mapping: 256 threads = 64 pos x 4 b-sub
    const int pe = tid >> 2;
    const int bi = tid & 3;
    const int je = j0 + (pe >> 3);
    const int be = b0 + ((pe & 7) << 2) + bi;

    for (int s = 0; s < Tt; ++s) {
        const float* hin  = g_h[s & 1];
        float*       hout = g_h[(s + 1) & 1];

        // stage h tile: sH[k][bl] = hin[k*128 + b0 + bl]  (float4)
        {
            const float4* src = (const float4*)hin;
            float4*       dst = (float4*)sH;
            #pragma unroll
            for (int i4 = tid; i4 < 2048; i4 += 256) {
                int k = i4 >> 3, q = i4 & 7;
                dst[i4] = src[(k << 5) + (b0 >> 2) + q];
            }
        }
        // prefetch G (DRAM) and c — latency hidden behind the GEMM
        float gp0 = g_G[(((size_t)s * 4 + 0) * 256 + je) * Bsz + be];
        float gp1 = g_G[(((size_t)s * 4 + 1) * 256 + je) * Bsz + be];
        float gp2 = g_G[(((size_t)s * 4 + 2) * 256 + je) * Bsz + be];
        float gp3 = g_G[(((size_t)s * 4 + 3) * 256 + je) * Bsz + be];
        float cold = g_c[(je << 7) + be];
        __syncthreads();

        // ---- packed f32x2 GEMM: 4b x 1j x 4gates over 64 k ----
        unsigned long long acc[8];
        #pragma unroll
        for (int a = 0; a < 8; ++a) acc[a] = 0ULL;

        #pragma unroll 8
        for (int kk = 0; kk < 64; ++kk) {
            int k = kb + kk;
            ulonglong2 hv = *(const ulonglong2*)(sH + (k << 5) + hoff);
            ulonglong2 wA = *(const ulonglong2*)(sW + (k << 6) + woff);
            ulonglong2 wB = *(const ulonglong2*)(sW + (k << 6) + woff + 4);
            fma2(acc[0], hv.x, wA.x); fma2(acc[1], hv.y, wA.x);
            fma2(acc[2], hv.x, wA.y); fma2(acc[3], hv.y, wA.y);
            fma2(acc[4], hv.x, wB.x); fma2(acc[5], hv.y, wB.x);
            fma2(acc[6], hv.x, wB.y); fma2(acc[7], hv.y, wB.y);
        }

        // ---- k-split reduction via padded shared (stride 72: conflict-free) ----
        #pragma unroll
        for (int g = 0; g < 4; ++g) {
            unsigned long long A0 = acc[g * 2], A1 = acc[g * 2 + 1];
            int base = ((ks << 4) + (g << 2)) * 72 + pos;
            sR[base]       = f2lo(A0);
            sR[base + 72]  = f2hi(A0);
            sR[base + 144] = f2lo(A1);
            sR[base + 216] = f2hi(A1);
        }
        __syncthreads();

        // ---- epilogue: sum splits, add G, LSTM cell update ----
        {
            float v0 = gp0, v1 = gp1, v2 = gp2, v3 = gp3;
            #pragma unroll
            for (int kss = 0; kss < 4; ++kss) {
                int base = ((kss << 4) + bi) * 72 + pe;
                v0 += sR[base];
                v1 += sR[base + 4 * 72];
                v2 += sR[base + 8 * 72];
                v3 += sR[base + 12 * 72];
            }
            float ig = sigf(v0), fg = sigf(v1);
            float gg = tanhf_(v2), og = sigf(v3);
            float cn = fg * cold + ig * gg;
            float hn = og * tanhf_(cn);
            g_c[(je << 7) + be]  = cn;
            hout[(je << 7) + be] = hn;
        }
        grid_bar();
    }

    // ---- classifier head: block = batch row b, thread = output o ----
    {
        const float* hf = g_h[0];            // final h lives in buffer 0 (T even)
        const int b = blockIdx.x;
        const int o = tid;
        if (o < OUTs) {
            float acc = b_fc[o];
            const float* wr = W_fc + o * Hh;
            #pragma unroll 8
            for (int k = 0; k < Hh; ++k)
                acc += hf[(k << 7) + b] * wr[k];
            out[b * OUTs + o] = acc;
        }
    }
}

// ---------------- launcher ----------------
extern "C" void kernel_launch(void* const* d_in, const int* in_sizes, int n_in,
                              void* d_out, int out_size) {
    const float* x    = (const float*)d_in[0];
    // d_in[1] = input_lengths (unused by the reference)
    const float* W_ih = (const float*)d_in[2];
    const float* W_hh = (const float*)d_in[3];
    const float* b_ih = (const float*)d_in[4];
    const float* b_hh = (const float*)d_in[5];
    // d_in[6], d_in[7] = W_xi, b_xi — dead code (memory never affects output)
    const float* W_fc = (const float*)d_in[8];
    const float* b_fc = (const float*)d_in[9];
    float* out = (float*)d_out;

    cudaFuncSetAttribute(step_kernel, cudaFuncAttributeMaxDynamicSharedMemorySize, 116736);

    init_kernel<<<128, 256>>>();
    pre_kernel<<<dim3(Tt, 8), 128>>>(x, W_ih, b_ih, b_hh);
    step_kernel<<<NB, 256, 116736>>>(W_hh, W_fc, b_fc, out);
}